// round 4
// baseline (speedup 1.0000x reference)
#include <cuda_runtime.h>
#include <math.h>

#define BB 4
#define NB 288
#define NC 32
#define NP 16
#define HW 196
#define EPSF 1e-5f

#define NVPHW (BB*NC*NP*HW)   // 401408
#define NCHW  (BB*NC*HW)      // 25088
#define NCHW4 (NCHW/4)        // 6272

// scratch (allocation-free: __device__ globals)
__device__ float    g_s[NVPHW];
__device__ float    g_v[NVPHW];
__device__ unsigned g_maxb[NCHW];
__device__ unsigned g_minb[NCHW];
__device__ float    g_inv[NCHW];

// ---------------------------------------------------------------------------
__global__ void k_init() {
    int i = blockIdx.x * blockDim.x + threadIdx.x;
    if (i < NCHW) { g_maxb[i] = 0u; g_minb[i] = 0x7F800000u; }
    if (i < NVPHW) g_s[i] = 0.0f;
}

// ---------------------------------------------------------------------------
// Pass A: pose norms -> max/min over B; s0_raw = sum_B u.
// grid (9 Bgroups of 32, 4 c-groups of 8, 4 b), 392 threads = (csub, q4)
__global__ void __launch_bounds__(392, 1) k_passA(const float* __restrict__ u) {
    int bg = blockIdx.x;          // 0..8
    int cg = blockIdx.y;          // 0..3
    int b  = blockIdx.z;          // 0..3
    int tid = threadIdx.x;
    int csub = tid / 49;          // 0..7
    int q4   = tid % 49;          // 0..48
    int c = cg * 8 + csub;
    int hwoff = q4 * 4;

    float4 sacc[NP];
#pragma unroll
    for (int p = 0; p < NP; p++) sacc[p] = make_float4(0.f, 0.f, 0.f, 0.f);
    float4 mx = make_float4(-1e30f, -1e30f, -1e30f, -1e30f);
    float4 mn = make_float4( 1e30f,  1e30f,  1e30f,  1e30f);

    for (int bi = 0; bi < 32; bi++) {
        int Bidx = bg * 32 + bi;
        const float* up = u + (((size_t)(b * NB + Bidx) * NC + c) * NP) * HW + hwoff;
        float4 n2 = make_float4(EPSF, EPSF, EPSF, EPSF);
#pragma unroll
        for (int p = 0; p < NP; p++) {
            float4 x = *(const float4*)(up + p * HW);
            sacc[p].x += x.x; sacc[p].y += x.y; sacc[p].z += x.z; sacc[p].w += x.w;
            n2.x += x.x * x.x; n2.y += x.y * x.y; n2.z += x.z * x.z; n2.w += x.w * x.w;
        }
        float4 nb = make_float4(sqrtf(n2.x), sqrtf(n2.y), sqrtf(n2.z), sqrtf(n2.w));
        mx.x = fmaxf(mx.x, nb.x); mx.y = fmaxf(mx.y, nb.y);
        mx.z = fmaxf(mx.z, nb.z); mx.w = fmaxf(mx.w, nb.w);
        mn.x = fminf(mn.x, nb.x); mn.y = fminf(mn.y, nb.y);
        mn.z = fminf(mn.z, nb.z); mn.w = fminf(mn.w, nb.w);
    }

    int mi = (b * NC + c) * HW + hwoff;
    atomicMax(&g_maxb[mi + 0], __float_as_uint(mx.x));
    atomicMax(&g_maxb[mi + 1], __float_as_uint(mx.y));
    atomicMax(&g_maxb[mi + 2], __float_as_uint(mx.z));
    atomicMax(&g_maxb[mi + 3], __float_as_uint(mx.w));
    atomicMin(&g_minb[mi + 0], __float_as_uint(mn.x));
    atomicMin(&g_minb[mi + 1], __float_as_uint(mn.y));
    atomicMin(&g_minb[mi + 2], __float_as_uint(mn.z));
    atomicMin(&g_minb[mi + 3], __float_as_uint(mn.w));

    int sbase = ((b * NC + c) * NP) * HW + hwoff;
#pragma unroll
    for (int p = 0; p < NP; p++) {
        atomicAdd(&g_s[sbase + p * HW + 0], sacc[p].x);
        atomicAdd(&g_s[sbase + p * HW + 1], sacc[p].y);
        atomicAdd(&g_s[sbase + p * HW + 2], sacc[p].z);
        atomicAdd(&g_s[sbase + p * HW + 3], sacc[p].w);
    }
}

// ---------------------------------------------------------------------------
// squash: one thread per (b,C,hw4)
// mode 0: compute inv, scale=inv/32, g_v  = squash, zero g_s
// mode 1: scale=inv,                 g_v += squash, zero g_s   (linearity trick)
// mode 2: scale=inv,                 write v + a_out to output
__global__ void k_squash(float* __restrict__ vout, float* __restrict__ aout, int mode) {
    int i = blockIdx.x * blockDim.x + threadIdx.x;
    if (i >= NCHW4) return;
    int bc = i / 49, q4 = i % 49;
    int mi = bc * HW + q4 * 4;

    float inv[4];
    if (mode == 0) {
#pragma unroll
        for (int j = 0; j < 4; j++) {
            float mxv = __uint_as_float(g_maxb[mi + j]);
            float mnv = __uint_as_float(g_minb[mi + j]);
            inv[j] = 1.0f / (mxv - mnv);
            g_inv[mi + j] = inv[j];
        }
    } else {
        float4 iv = *(const float4*)&g_inv[mi];
        inv[0] = iv.x; inv[1] = iv.y; inv[2] = iv.z; inv[3] = iv.w;
    }
    float mul = (mode == 0) ? (1.0f / 32.0f) : 1.0f;
    float sc[4];
#pragma unroll
    for (int j = 0; j < 4; j++) sc[j] = inv[j] * mul;

    int sbase = bc * NP * HW + q4 * 4;
    float sv[NP][4];
    float n2[4] = {EPSF, EPSF, EPSF, EPSF};
#pragma unroll
    for (int p = 0; p < NP; p++) {
        float4 x = *(const float4*)&g_s[sbase + p * HW];
        float xs[4] = {x.x * sc[0], x.y * sc[1], x.z * sc[2], x.w * sc[3]};
#pragma unroll
        for (int j = 0; j < 4; j++) { sv[p][j] = xs[j]; n2[j] += xs[j] * xs[j]; }
    }
    float f[4];
#pragma unroll
    for (int j = 0; j < 4; j++) f[j] = 1.0f / (1.0f + sqrtf(n2[j]));

    if (mode < 2) {
#pragma unroll
        for (int p = 0; p < NP; p++) {
            float4 vold = make_float4(0.f, 0.f, 0.f, 0.f);
            if (mode == 1) vold = *(const float4*)&g_v[sbase + p * HW];
            float4 vn;
            vn.x = vold.x + sv[p][0] * f[0];
            vn.y = vold.y + sv[p][1] * f[1];
            vn.z = vold.z + sv[p][2] * f[2];
            vn.w = vold.w + sv[p][3] * f[3];
            *(float4*)&g_v[sbase + p * HW] = vn;
            *(float4*)&g_s[sbase + p * HW] = make_float4(0.f, 0.f, 0.f, 0.f);
        }
    } else {
        float av2[4] = {EPSF, EPSF, EPSF, EPSF};
#pragma unroll
        for (int p = 0; p < NP; p++) {
            float4 vn;
            vn.x = sv[p][0] * f[0]; vn.y = sv[p][1] * f[1];
            vn.z = sv[p][2] * f[2]; vn.w = sv[p][3] * f[3];
            *(float4*)&vout[sbase + p * HW] = vn;
            av2[0] += vn.x * vn.x; av2[1] += vn.y * vn.y;
            av2[2] += vn.z * vn.z; av2[3] += vn.w * vn.w;
        }
#pragma unroll
        for (int j = 0; j < 4; j++) aout[mi + j] = sqrtf(av2[j]);
    }
}

// ---------------------------------------------------------------------------
// Routing pass v5. grid (9 Bgroups of 32, 7 hw-chunks of 28, 4 b), 448 threads.
// thread tid = q4*64 + c*2 + ph: owns 1 C x 8 P (ph half) x 4 hw.
//   - v, inv, u, acc all in REGISTERS; no v smem at all.
//   - full r via shfl_xor(1) with the ph-partner (adjacent lane).
//   - softmax denominator: warp butterfly over its 16 c (shfl_xor 2,4,8,16),
//     then a 2-warp exchange through tiny smem, synced by a NAMED barrier
//     scoped to the 64-thread q4 group (groups run decoupled!).
//   - parity double-buffer on the exchange slots -> 1 barrier per bi.
#define RTH 448

__global__ void __launch_bounds__(RTH, 1) k_route(const float* __restrict__ u) {
    __shared__ float4 part_sh[2][7][2];   // [bi parity][q4][warp half]

    int bg = blockIdx.x;   // 0..8
    int hq = blockIdx.y;   // 0..6
    int b  = blockIdx.z;   // 0..3
    int tid = threadIdx.x;
    int q4 = tid >> 6;            // 0..6
    int cp = tid & 63;
    int c  = cp >> 1;             // 0..31
    int ph = cp & 1;              // 0..1
    int half = (tid >> 5) & 1;    // which warp of the q4 group
    int hwoff = hq * 28 + q4 * 4;
    int bid = q4 + 1;             // named barrier id 1..7

    // v (bi-invariant) and inv into registers
    const float* vb = g_v + ((size_t)((b * NC + c) * NP + ph * 8)) * HW + hwoff;
    float4 v4[8];
#pragma unroll
    for (int p = 0; p < 8; p++) v4[p] = *(const float4*)(vb + p * HW);
    float4 invv = *(const float4*)&g_inv[(b * NC + c) * HW + hwoff];

    float4 acc[8];
#pragma unroll
    for (int p = 0; p < 8; p++) acc[p] = make_float4(0.f, 0.f, 0.f, 0.f);

    const float* ub = u + ((((size_t)(b * NB + bg * 32) * NC + c) * NP) + ph * 8) * HW + hwoff;

    for (int bi = 0; bi < 32; bi++) {
        const float* up = ub + (size_t)bi * (NC * NP * HW);
        float4 u4[8];
#pragma unroll
        for (int p = 0; p < 8; p++) u4[p] = *(const float4*)(up + p * HW);

        // partial agreement over this thread's 8 P
        float4 r = make_float4(0.f, 0.f, 0.f, 0.f);
#pragma unroll
        for (int p = 0; p < 8; p++) {
            r.x += u4[p].x * v4[p].x; r.y += u4[p].y * v4[p].y;
            r.z += u4[p].z * v4[p].z; r.w += u4[p].w * v4[p].w;
        }
        // full r: add ph-partner's half (adjacent lane)
        r.x += __shfl_xor_sync(0xffffffffu, r.x, 1);
        r.y += __shfl_xor_sync(0xffffffffu, r.y, 1);
        r.z += __shfl_xor_sync(0xffffffffu, r.z, 1);
        r.w += __shfl_xor_sync(0xffffffffu, r.w, 1);

        // softmax numerator (|r*inv| small: safe without max subtraction)
        float4 e;
        e.x = __expf(r.x * invv.x); e.y = __expf(r.y * invv.y);
        e.z = __expf(r.z * invv.z); e.w = __expf(r.w * invv.w);

        // butterfly sum over this warp's 16 c (bit0 pairs hold identical e)
        float4 s4 = e;
#pragma unroll
        for (int m = 2; m <= 16; m <<= 1) {
            s4.x += __shfl_xor_sync(0xffffffffu, s4.x, m);
            s4.y += __shfl_xor_sync(0xffffffffu, s4.y, m);
            s4.z += __shfl_xor_sync(0xffffffffu, s4.z, m);
            s4.w += __shfl_xor_sync(0xffffffffu, s4.w, m);
        }
        // butterfly included xor1 pairs? no: masks 2..16 only -> s4 = sum over
        // the 16 c of this warp (e identical across ph so value is exact).
        if ((tid & 31) == 0) part_sh[bi & 1][q4][half] = s4;
        asm volatile("bar.sync %0, %1;" :: "r"(bid), "r"(64) : "memory");
        float4 o = part_sh[bi & 1][q4][half ^ 1];
        float4 d;
        d.x = __frcp_rn(s4.x + o.x); d.y = __frcp_rn(s4.y + o.y);
        d.z = __frcp_rn(s4.z + o.z); d.w = __frcp_rn(s4.w + o.w);

        float4 cv;
        cv.x = e.x * d.x; cv.y = e.y * d.y;
        cv.z = e.z * d.z; cv.w = e.w * d.w;

#pragma unroll
        for (int p = 0; p < 8; p++) {
            acc[p].x += cv.x * u4[p].x; acc[p].y += cv.y * u4[p].y;
            acc[p].z += cv.z * u4[p].z; acc[p].w += cv.w * u4[p].w;
        }
    }

    int sbase = ((b * NC + c) * NP + ph * 8) * HW + hwoff;
#pragma unroll
    for (int p = 0; p < 8; p++) {
        atomicAdd(&g_s[sbase + p * HW + 0], acc[p].x);
        atomicAdd(&g_s[sbase + p * HW + 1], acc[p].y);
        atomicAdd(&g_s[sbase + p * HW + 2], acc[p].z);
        atomicAdd(&g_s[sbase + p * HW + 3], acc[p].w);
    }
}

// ---------------------------------------------------------------------------
extern "C" void kernel_launch(void* const* d_in, const int* in_sizes, int n_in,
                              void* d_out, int out_size) {
    const float* u = (const float*)d_in[0];   // (4,288,32,16,14,14)
    float* out  = (float*)d_out;
    float* vout = out;                        // (4,32,16,14,14)
    float* aout = out + NVPHW;                // (4,32,14,14)

    k_init<<<(NVPHW + 255) / 256, 256>>>();
    k_passA<<<dim3(9, 4, 4), 392>>>(u);
    k_squash<<<(NCHW4 + 255) / 256, 256>>>(nullptr, nullptr, 0);  // v0 = squash(s0)
    k_route<<<dim3(9, 7, 4), RTH>>>(u);                           // s1 (uses v0)
    k_squash<<<(NCHW4 + 255) / 256, 256>>>(nullptr, nullptr, 1);  // g_v = v0+v1
    k_route<<<dim3(9, 7, 4), RTH>>>(u);                           // s2 (uses v0+v1)
    k_squash<<<(NCHW4 + 255) / 256, 256>>>(vout, aout, 2);        // v2, a_out
}

// round 7
// speedup vs baseline: 1.3465x; 1.3465x over previous
#include <cuda_runtime.h>
#include <math.h>

#define BB 4
#define NB 288
#define NC 32
#define NP 16
#define HW 196
#define EPSF 1e-5f

#define NVPHW (BB*NC*NP*HW)   // 401408
#define NCHW  (BB*NC*HW)      // 25088
#define NCHW4 (NCHW/4)        // 6272

// scratch (allocation-free: __device__ globals)
__device__ float    g_s[NVPHW];
__device__ float    g_v[NVPHW];
__device__ unsigned g_maxb[NCHW];
__device__ unsigned g_minb[NCHW];
__device__ float    g_inv[NCHW];

// ---------------------------------------------------------------------------
__global__ void k_init() {
    int i = blockIdx.x * blockDim.x + threadIdx.x;
    if (i < NCHW) { g_maxb[i] = 0u; g_minb[i] = 0x7F800000u; }
    if (i < NVPHW) g_s[i] = 0.0f;
}

// ---------------------------------------------------------------------------
// Pass A: pose norms -> max/min over B; s0_raw = sum_B u.
// grid (9 Bgroups of 32, 4 c-groups of 8, 4 b), 392 threads = (csub, q4)
__global__ void __launch_bounds__(392, 1) k_passA(const float* __restrict__ u) {
    int bg = blockIdx.x;          // 0..8
    int cg = blockIdx.y;          // 0..3
    int b  = blockIdx.z;          // 0..3
    int tid = threadIdx.x;
    int csub = tid / 49;          // 0..7
    int q4   = tid % 49;          // 0..48
    int c = cg * 8 + csub;
    int hwoff = q4 * 4;

    float4 sacc[NP];
#pragma unroll
    for (int p = 0; p < NP; p++) sacc[p] = make_float4(0.f, 0.f, 0.f, 0.f);
    float4 mx = make_float4(-1e30f, -1e30f, -1e30f, -1e30f);
    float4 mn = make_float4( 1e30f,  1e30f,  1e30f,  1e30f);

    for (int bi = 0; bi < 32; bi++) {
        int Bidx = bg * 32 + bi;
        const float* up = u + (((size_t)(b * NB + Bidx) * NC + c) * NP) * HW + hwoff;
        float4 n2 = make_float4(EPSF, EPSF, EPSF, EPSF);
#pragma unroll
        for (int p = 0; p < NP; p++) {
            float4 x = *(const float4*)(up + p * HW);
            sacc[p].x += x.x; sacc[p].y += x.y; sacc[p].z += x.z; sacc[p].w += x.w;
            n2.x += x.x * x.x; n2.y += x.y * x.y; n2.z += x.z * x.z; n2.w += x.w * x.w;
        }
        float4 nb = make_float4(sqrtf(n2.x), sqrtf(n2.y), sqrtf(n2.z), sqrtf(n2.w));
        mx.x = fmaxf(mx.x, nb.x); mx.y = fmaxf(mx.y, nb.y);
        mx.z = fmaxf(mx.z, nb.z); mx.w = fmaxf(mx.w, nb.w);
        mn.x = fminf(mn.x, nb.x); mn.y = fminf(mn.y, nb.y);
        mn.z = fminf(mn.z, nb.z); mn.w = fminf(mn.w, nb.w);
    }

    int mi = (b * NC + c) * HW + hwoff;
    atomicMax(&g_maxb[mi + 0], __float_as_uint(mx.x));
    atomicMax(&g_maxb[mi + 1], __float_as_uint(mx.y));
    atomicMax(&g_maxb[mi + 2], __float_as_uint(mx.z));
    atomicMax(&g_maxb[mi + 3], __float_as_uint(mx.w));
    atomicMin(&g_minb[mi + 0], __float_as_uint(mn.x));
    atomicMin(&g_minb[mi + 1], __float_as_uint(mn.y));
    atomicMin(&g_minb[mi + 2], __float_as_uint(mn.z));
    atomicMin(&g_minb[mi + 3], __float_as_uint(mn.w));

    int sbase = ((b * NC + c) * NP) * HW + hwoff;
#pragma unroll
    for (int p = 0; p < NP; p++) {
        atomicAdd(&g_s[sbase + p * HW + 0], sacc[p].x);
        atomicAdd(&g_s[sbase + p * HW + 1], sacc[p].y);
        atomicAdd(&g_s[sbase + p * HW + 2], sacc[p].z);
        atomicAdd(&g_s[sbase + p * HW + 3], sacc[p].w);
    }
}

// ---------------------------------------------------------------------------
// squash: one thread per (b,C,hw4)
// mode 0: compute inv, scale=inv/32, g_v  = squash, zero g_s
// mode 1: scale=inv,                 g_v += squash, zero g_s   (linearity trick)
// mode 2: scale=inv,                 write v + a_out to output
__global__ void k_squash(float* __restrict__ vout, float* __restrict__ aout, int mode) {
    int i = blockIdx.x * blockDim.x + threadIdx.x;
    if (i >= NCHW4) return;
    int bc = i / 49, q4 = i % 49;
    int mi = bc * HW + q4 * 4;

    float inv[4];
    if (mode == 0) {
#pragma unroll
        for (int j = 0; j < 4; j++) {
            float mxv = __uint_as_float(g_maxb[mi + j]);
            float mnv = __uint_as_float(g_minb[mi + j]);
            inv[j] = 1.0f / (mxv - mnv);
            g_inv[mi + j] = inv[j];
        }
    } else {
        float4 iv = *(const float4*)&g_inv[mi];
        inv[0] = iv.x; inv[1] = iv.y; inv[2] = iv.z; inv[3] = iv.w;
    }
    float mul = (mode == 0) ? (1.0f / 32.0f) : 1.0f;
    float sc[4];
#pragma unroll
    for (int j = 0; j < 4; j++) sc[j] = inv[j] * mul;

    int sbase = bc * NP * HW + q4 * 4;
    float sv[NP][4];
    float n2[4] = {EPSF, EPSF, EPSF, EPSF};
#pragma unroll
    for (int p = 0; p < NP; p++) {
        float4 x = *(const float4*)&g_s[sbase + p * HW];
        float xs[4] = {x.x * sc[0], x.y * sc[1], x.z * sc[2], x.w * sc[3]};
#pragma unroll
        for (int j = 0; j < 4; j++) { sv[p][j] = xs[j]; n2[j] += xs[j] * xs[j]; }
    }
    float f[4];
#pragma unroll
    for (int j = 0; j < 4; j++) f[j] = 1.0f / (1.0f + sqrtf(n2[j]));

    if (mode < 2) {
#pragma unroll
        for (int p = 0; p < NP; p++) {
            float4 vold = make_float4(0.f, 0.f, 0.f, 0.f);
            if (mode == 1) vold = *(const float4*)&g_v[sbase + p * HW];
            float4 vn;
            vn.x = vold.x + sv[p][0] * f[0];
            vn.y = vold.y + sv[p][1] * f[1];
            vn.z = vold.z + sv[p][2] * f[2];
            vn.w = vold.w + sv[p][3] * f[3];
            *(float4*)&g_v[sbase + p * HW] = vn;
            *(float4*)&g_s[sbase + p * HW] = make_float4(0.f, 0.f, 0.f, 0.f);
        }
    } else {
        float av2[4] = {EPSF, EPSF, EPSF, EPSF};
#pragma unroll
        for (int p = 0; p < NP; p++) {
            float4 vn;
            vn.x = sv[p][0] * f[0]; vn.y = sv[p][1] * f[1];
            vn.z = sv[p][2] * f[2]; vn.w = sv[p][3] * f[3];
            *(float4*)&vout[sbase + p * HW] = vn;
            av2[0] += vn.x * vn.x; av2[1] += vn.y * vn.y;
            av2[2] += vn.z * vn.z; av2[3] += vn.w * vn.w;
        }
#pragma unroll
        for (int j = 0; j < 4; j++) aout[mi + j] = sqrtf(av2[j]);
    }
}

// ---------------------------------------------------------------------------
// Routing pass v6. grid (9 Bgroups of 32, 14 hw-chunks of 14, 4 b), 224 thr.
// thread tid = c*7 + q2: owns 1 C x 16 P x 2 hw (float2).
//   - hw varies fastest in-warp (runs of 7 float2 per c-row) -> good nL.
//   - v, inv, u, acc in registers; ~126 regs -> TWO blocks per SM:
//     decoupled barrier domains keep LDGs in flight during softmax reduce.
//   - softmax: e -> tiny smem, 14 reducer lanes sum 32 c (conflict-free),
//     2 barriers/bi over only 7 warps.
#define RTH 224

__global__ void __launch_bounds__(RTH, 2) k_route(const float* __restrict__ u) {
    __shared__ float e_sh[NC][18];   // stride 18 floats (pad: c,c+16 alias only)
    __shared__ float dinv_sh[16];

    int bg = blockIdx.x;   // 0..8
    int hq = blockIdx.y;   // 0..13
    int b  = blockIdx.z;   // 0..3
    int tid = threadIdx.x;
    int c  = tid / 7;             // 0..31
    int q2 = tid % 7;             // 0..6
    int hwoff = hq * 14 + q2 * 2;

    // v (bi-invariant) and inv into registers
    const float* vb = g_v + ((size_t)(b * NC + c) * NP) * HW + hwoff;
    float2 v2[NP];
#pragma unroll
    for (int p = 0; p < NP; p++) v2[p] = *(const float2*)(vb + p * HW);
    float2 invv = *(const float2*)&g_inv[(b * NC + c) * HW + hwoff];

    float2 acc[NP];
#pragma unroll
    for (int p = 0; p < NP; p++) acc[p] = make_float2(0.f, 0.f);

    const float* ub = u + ((size_t)(b * NB + bg * 32) * NC + c) * NP * HW + hwoff;

    for (int bi = 0; bi < 32; bi++) {
        const float* up = ub + (size_t)bi * (NC * NP * HW);
        float2 u2[NP];
#pragma unroll
        for (int p = 0; p < NP; p++) u2[p] = *(const float2*)(up + p * HW);

        // agreement r = sum_P u.v (registers), scaled by inv
        float rx = 0.f, ry = 0.f;
#pragma unroll
        for (int p = 0; p < NP; p++) {
            rx += u2[p].x * v2[p].x;
            ry += u2[p].y * v2[p].y;
        }
        // softmax numerator (|r*inv| small: safe without max subtraction)
        float ex = __expf(rx * invv.x);
        float ey = __expf(ry * invv.y);
        *(float2*)&e_sh[c][2 * q2] = make_float2(ex, ey);
        __syncthreads();

        if (tid < 14) {
            float s = 0.f;
#pragma unroll
            for (int cc = 0; cc < NC; cc++) s += e_sh[cc][tid];
            dinv_sh[tid] = __frcp_rn(s);
        }
        __syncthreads();

        float2 d = *(const float2*)&dinv_sh[2 * q2];
        float cx = ex * d.x;
        float cy = ey * d.y;

#pragma unroll
        for (int p = 0; p < NP; p++) {
            acc[p].x += cx * u2[p].x;
            acc[p].y += cy * u2[p].y;
        }
    }

    int sbase = ((b * NC + c) * NP) * HW + hwoff;
#pragma unroll
    for (int p = 0; p < NP; p++) {
        atomicAdd(&g_s[sbase + p * HW + 0], acc[p].x);
        atomicAdd(&g_s[sbase + p * HW + 1], acc[p].y);
    }
}

// ---------------------------------------------------------------------------
extern "C" void kernel_launch(void* const* d_in, const int* in_sizes, int n_in,
                              void* d_out, int out_size) {
    const float* u = (const float*)d_in[0];   // (4,288,32,16,14,14)
    float* out  = (float*)d_out;
    float* vout = out;                        // (4,32,16,14,14)
    float* aout = out + NVPHW;                // (4,32,14,14)

    k_init<<<(NVPHW + 255) / 256, 256>>>();
    k_passA<<<dim3(9, 4, 4), 392>>>(u);
    k_squash<<<(NCHW4 + 255) / 256, 256>>>(nullptr, nullptr, 0);  // v0 = squash(s0)
    k_route<<<dim3(9, 14, 4), RTH>>>(u);                          // s1 (uses v0)
    k_squash<<<(NCHW4 + 255) / 256, 256>>>(nullptr, nullptr, 1);  // g_v = v0+v1
    k_route<<<dim3(9, 14, 4), RTH>>>(u);                          // s2 (uses v0+v1)
    k_squash<<<(NCHW4 + 255) / 256, 256>>>(vout, aout, 2);        // v2, a_out
}